// round 1
// baseline (speedup 1.0000x reference)
#include <cuda_runtime.h>

#define PDIM     512
#define TILE     128
#define KCHUNK   32
#define NTHREADS 256

__device__ __forceinline__ float clamp01f(float v) {
    return fminf(fmaxf(v, 0.0f), 1.0f);
}

// out[b, img, p, q] = sum_k u_k(p) * h_k(q)
//   img==0 (hilbert, K=64):
//     k<32 : X = a0/SIDE,            Y = b0/SIDE
//     k>=32: X = b1/SIDE - 512,      Y = a1/SIDE
//     h[q] = clamp(min(q+1-X, Y-q), 0, 1)
//     u[p] = clamp(min(512-p-Y, X+1+p), 0, 1)
//   img==1 (rank invariant, K=32):
//     X = a0/SIDE, Y = b0/SIDE
//     h[q] = clamp(q+1-X, 0, 1)
//     u[p] = clamp(Y-511+p, 0, 1)
__global__ __launch_bounds__(NTHREADS, 2)
void hilbert_raster_kernel(const float* __restrict__ iv00,
                           const float* __restrict__ iv01,
                           float* __restrict__ out)
{
    __shared__ float Xs[64], Ys[64];
    __shared__ float Us[KCHUNK][TILE];   // vert factors for this p-tile, k-major
    __shared__ float Hs[KCHUNK][TILE];   // hor  factors for this q-tile, k-major

    const int t   = threadIdx.x;
    const int z   = blockIdx.z;      // 0..511  = batch*2 + img
    const int b   = z >> 1;
    const int img = z & 1;
    const int q0  = blockIdx.x * TILE;
    const int p0  = blockIdx.y * TILE;

    const float INV_SIDE = 325.94932345220167f;  // 1024/pi = 1/SIDE

    if (t < 64) {
        const int k = t;
        float X = 1e9f, Y = -1e9f;
        if (img == 0) {
            if (k < 32) {
                X = iv00[(b * 32 + k) * 2 + 0] * INV_SIDE;
                Y = iv00[(b * 32 + k) * 2 + 1] * INV_SIDE;
            } else {
                X = iv01[(b * 32 + (k - 32)) * 2 + 1] * INV_SIDE - 512.0f;
                Y = iv01[(b * 32 + (k - 32)) * 2 + 0] * INV_SIDE;
            }
        } else if (k < 32) {
            X = iv00[(b * 32 + k) * 2 + 0] * INV_SIDE;
            Y = iv00[(b * 32 + k) * 2 + 1] * INV_SIDE;
        }
        Xs[k] = X;
        Ys[k] = Y;
    }

    const int tx = t & 15;   // q direction (16 threads)
    const int ty = t >> 4;   // p direction (16 threads)

    float acc[8][8];
    #pragma unroll
    for (int i = 0; i < 8; ++i)
        #pragma unroll
        for (int j = 0; j < 8; ++j)
            acc[i][j] = 0.0f;

    const int Keff = (img == 0) ? 64 : 32;

    for (int kb = 0; kb < Keff; kb += KCHUNK) {
        __syncthreads();
        // ---- generate factor tiles for k in [kb, kb+KCHUNK) ----
        #pragma unroll
        for (int it = 0; it < (KCHUNK * TILE) / NTHREADS; ++it) {
            int idx = t + it * NTHREADS;
            int k = idx >> 7;            // TILE == 128
            int j = idx & (TILE - 1);
            float X = Xs[kb + k];
            float Y = Ys[kb + k];
            float fq = (float)(q0 + j);
            float fp = (float)(p0 + j);
            float u, h;
            if (img == 0) {
                h = clamp01f(fminf(fq + 1.0f - X, Y - fq));
                u = clamp01f(fminf(512.0f - fp - Y, X + 1.0f + fp));
            } else {
                h = clamp01f(fq + 1.0f - X);
                u = clamp01f(Y - 511.0f + fp);
            }
            Us[k][j] = u;
            Hs[k][j] = h;
        }
        __syncthreads();

        // ---- rank-KCHUNK update of the 128x128 tile ----
        #pragma unroll
        for (int k = 0; k < KCHUNK; ++k) {
            float4 u0 = *reinterpret_cast<const float4*>(&Us[k][ty * 4]);
            float4 u1 = *reinterpret_cast<const float4*>(&Us[k][ty * 4 + 64]);
            float4 h0 = *reinterpret_cast<const float4*>(&Hs[k][tx * 4]);
            float4 h1 = *reinterpret_cast<const float4*>(&Hs[k][tx * 4 + 64]);
            float u[8] = {u0.x, u0.y, u0.z, u0.w, u1.x, u1.y, u1.z, u1.w};
            float h[8] = {h0.x, h0.y, h0.z, h0.w, h1.x, h1.y, h1.z, h1.w};
            #pragma unroll
            for (int i = 0; i < 8; ++i)
                #pragma unroll
                for (int j = 0; j < 8; ++j)
                    acc[i][j] = fmaf(u[i], h[j], acc[i][j]);
        }
    }

    // ---- store 8x8 per thread, coalesced float4 ----
    const size_t base = (size_t)z * PDIM * PDIM;
    #pragma unroll
    for (int i = 0; i < 8; ++i) {
        int p = p0 + ty * 4 + (i & 3) + ((i >= 4) ? 64 : 0);
        float* row = out + base + (size_t)p * PDIM + q0;
        *reinterpret_cast<float4*>(row + tx * 4) =
            make_float4(acc[i][0], acc[i][1], acc[i][2], acc[i][3]);
        *reinterpret_cast<float4*>(row + 64 + tx * 4) =
            make_float4(acc[i][4], acc[i][5], acc[i][6], acc[i][7]);
    }
}

extern "C" void kernel_launch(void* const* d_in, const int* in_sizes, int n_in,
                              void* d_out, int out_size)
{
    const float* iv00 = (const float*)d_in[0];   // intervals00 (256,32,2)
    const float* iv01 = (const float*)d_in[1];   // intervals01 (256,32,2)
    float* out = (float*)d_out;                  // (256,2,512,512) fp32

    dim3 grid(PDIM / TILE, PDIM / TILE, 512);
    hilbert_raster_kernel<<<grid, NTHREADS>>>(iv00, iv01, out);
}